// round 5
// baseline (speedup 1.0000x reference)
#include <cuda_runtime.h>
#include <cuda_fp16.h>
#include <cstdint>

#define NPT   120000
#define HID   128
#define INP   320
#define CINL  448
#define KOFF  28
#define KTOT  (KOFF * CINL)     // 12544
#define NCHUNK (KOFF * 7)       // 196 chunks of K=64
#define STAGES 4

// ---------------- device scratch ----------------
__device__ __half g_HX [(size_t)NPT * CINL];
__device__ __half g_RX [(size_t)NPT * CINL];
__device__ float  g_Z  [(size_t)NPT * HID];
__device__ __half g_Wzr[(size_t)256 * KTOT];   // [n][k*448+c]  n<128: z, n>=128: r
__device__ __half g_Wq [(size_t)128 * KTOT];   // [n][k*448+c]

// ---------------- asm helpers ----------------
__device__ __forceinline__ uint32_t smem_u32(const void* p) {
    uint32_t a;
    asm("{ .reg .u64 t; cvta.to.shared.u64 t, %1; cvt.u32.u64 %0, t; }" : "=r"(a) : "l"(p));
    return a;
}
__device__ __forceinline__ void cp16(uint32_t dst, const void* src, int sz) {
    asm volatile("cp.async.cg.shared.global [%0], [%1], 16, %2;"
                 :: "r"(dst), "l"(src), "r"(sz) : "memory");
}
#define CP_COMMIT() asm volatile("cp.async.commit_group;" ::: "memory")
#define CP_WAIT2()  asm volatile("cp.async.wait_group 2;" ::: "memory")

#define LDSM_X4(r0, r1, r2, r3, addr) \
    asm volatile("ldmatrix.sync.aligned.m8n8.x4.shared.b16 {%0,%1,%2,%3}, [%4];" \
        : "=r"(r0), "=r"(r1), "=r"(r2), "=r"(r3) : "r"(addr))

__device__ __forceinline__ void mma16816(float* d, const uint32_t* a, uint32_t b0, uint32_t b1) {
    asm volatile(
        "mma.sync.aligned.m16n8k16.row.col.f32.f16.f16.f32 "
        "{%0,%1,%2,%3}, {%4,%5,%6,%7}, {%8,%9}, {%0,%1,%2,%3};"
        : "+f"(d[0]), "+f"(d[1]), "+f"(d[2]), "+f"(d[3])
        : "r"(a[0]), "r"(a[1]), "r"(a[2]), "r"(a[3]), "r"(b0), "r"(b1));
}

// ---------------- packing kernels ----------------
__global__ void pack_inputs(const float* __restrict__ h, const float* __restrict__ x, int N) {
    size_t idx = (size_t)blockIdx.x * blockDim.x + threadIdx.x;
    size_t total = (size_t)N * CINL;
    if (idx >= total) return;
    int c = (int)(idx % CINL);
    size_t n = idx / CINL;
    float v = (c < HID) ? h[n * HID + c] : x[n * INP + (c - HID)];
    __half hv = __float2half_rn(v);
    g_HX[idx] = hv;
    if (c >= HID) g_RX[idx] = hv;
}

__global__ void pack_wzr(const float* __restrict__ Wz, const float* __restrict__ Wz_pt,
                         const float* __restrict__ Wr, const float* __restrict__ Wr_pt) {
    size_t idx = (size_t)blockIdx.x * blockDim.x + threadIdx.x;
    size_t total = (size_t)256 * KTOT;
    if (idx >= total) return;
    int rem = (int)(idx % KTOT);
    int n = (int)(idx / KTOT);
    int k = rem / CINL;
    int c = rem % CINL;
    float v;
    if (n < HID) v = (k < 27) ? Wz[((size_t)k * CINL + c) * HID + n] : Wz_pt[(size_t)c * HID + n];
    else {
        int m = n - HID;
        v = (k < 27) ? Wr[((size_t)k * CINL + c) * HID + m] : Wr_pt[(size_t)c * HID + m];
    }
    g_Wzr[idx] = __float2half_rn(v);
}

__global__ void pack_wq(const float* __restrict__ Wq, const float* __restrict__ Wq_pt) {
    size_t idx = (size_t)blockIdx.x * blockDim.x + threadIdx.x;
    size_t total = (size_t)128 * KTOT;
    if (idx >= total) return;
    int rem = (int)(idx % KTOT);
    int n = (int)(idx / KTOT);
    int k = rem / CINL;
    int c = rem % CINL;
    float v = (k < 27) ? Wq[((size_t)k * CINL + c) * HID + n] : Wq_pt[(size_t)c * HID + n];
    g_Wq[idx] = __float2half_rn(v);
}

// ---------------- main GEMM kernel ----------------
// 8 warps, warp tile 64x64. PASS1: BM=128(WM=2) x BN=256(WN=4), A=g_HX, B=g_Wzr
// (cols 0-127 = z, 128-255 = r, fused). PASS2: BM=256(WM=4) x BN=128(WN=2),
// A=g_RX, B=g_Wq.
template <int PASS, int WM, int WN>
__global__ void __launch_bounds__(256, 1)
sconv_mma(const int* __restrict__ nbr, const float* __restrict__ h,
          const float* __restrict__ b0, const float* __restrict__ b1,
          float* __restrict__ out, int N) {
    constexpr int BM = WM * 64;
    constexpr int BN = WN * 64;
    constexpr int A_BYTES = BM * 128;
    constexpr int STAGE_BYTES = (BM + BN) * 128;   // 49152 both passes

    extern __shared__ __align__(128) char dynsmem[];

    const int tid  = threadIdx.x;
    const int wid  = tid >> 5;
    const int lane = tid & 31;
    const int wm   = wid / WN;          // 0..WM-1
    const int wn   = wid % WN;          // 0..WN-1
    const int grp  = lane >> 2;
    const int tg   = lane & 3;
    const int i0   = blockIdx.x * BM;

    const __half* __restrict__ Asrc = (PASS == 1) ? g_HX : g_RX;
    const __half* __restrict__ WB   = (PASS == 1) ? g_Wzr : g_Wq;

    const uint32_t dsm_raw = smem_u32(dynsmem);
    const uint32_t dsm = (dsm_raw + 127u) & ~127u;

    // ---- prefetch constants (256 threads) ----
    // A: BM rows x 8 segs of 16B; B: BN rows x 8 segs
    constexpr int ASEGS = (BM == 128) ? 4 : 8;
    constexpr int BSEGS = (BN == 128) ? 4 : 8;
    const int  arow  = (BM == 128) ? (tid >> 1) : tid;
    const int  aseg0 = (BM == 128) ? ((tid & 1) * 4) : 0;
    const uint32_t axm = (uint32_t)((arow & 7) << 4);
    const int  g = i0 + arow;

    const int  brow  = (BN == 128) ? (tid >> 1) : tid;
    const int  bseg0 = (BN == 128) ? ((tid & 1) * 4) : 0;
    const uint32_t bxm = (uint32_t)((brow & 7) << 4);
    const __half* pbrow = WB + (size_t)brow * KTOT;

    int    cur_k = -1;
    int    asz   = 0;
    size_t aoff  = 0;

    // ---- ldmatrix lane constants ----
    const int sel = lane >> 3;                      // 0..3
    const uint32_t lxm = (uint32_t)((lane & 7) << 4);
    const uint32_t a_row_off =
        (uint32_t)(wm * 64 + (sel & 1) * 8 + (lane & 7)) * 128;
    const uint32_t a_cs16 = (uint32_t)((sel >> 1) * 16);
    const uint32_t b_row_off =
        (uint32_t)(wn * 64 + (sel >> 1) * 8 + (lane & 7)) * 128;
    const uint32_t b_cs16 = (uint32_t)((sel & 1) * 16);

    float acc[4][8][4];
#pragma unroll
    for (int a = 0; a < 4; ++a)
#pragma unroll
        for (int b = 0; b < 8; ++b)
#pragma unroll
            for (int c = 0; c < 4; ++c) acc[a][b][c] = 0.f;

    // ---- prefetch lambda ----
    auto do_prefetch = [&](int j) {
        const int k  = j / 7;
        const int cc = (j % 7) * 64;
        const int s  = j & (STAGES - 1);
        if (k != cur_k) {
            cur_k = k;
            int id = -1;
            if (g < N) id = (k == 27) ? g : nbr[(size_t)g * 27 + k];
            asz  = (id >= 0) ? 16 : 0;
            aoff = (size_t)((id >= 0) ? id : 0) * CINL;
        }
        const uint32_t sb = dsm + s * STAGE_BYTES;
        const __half* pa = Asrc + aoff + cc + aseg0 * 8;
        const uint32_t da = sb + (uint32_t)arow * 128;
#pragma unroll
        for (int t = 0; t < ASEGS; ++t) {
            const uint32_t so = (uint32_t)((aseg0 + t) * 16) ^ axm;
            cp16(da + so, pa + t * 8, asz);
        }
        const __half* pb = pbrow + (size_t)k * CINL + cc + bseg0 * 8;
        const uint32_t db = sb + A_BYTES + (uint32_t)brow * 128;
#pragma unroll
        for (int t = 0; t < BSEGS; ++t) {
            const uint32_t so = (uint32_t)((bseg0 + t) * 16) ^ bxm;
            cp16(db + so, pb + t * 8, 16);
        }
    };

    do_prefetch(0); CP_COMMIT();
    do_prefetch(1); CP_COMMIT();
    do_prefetch(2); CP_COMMIT();

    for (int i = 0; i < NCHUNK; ++i) {
        CP_WAIT2();
        __syncthreads();

        const uint32_t sb = dsm + (i & (STAGES - 1)) * STAGE_BYTES;
        const uint32_t aB = sb + a_row_off;
        const uint32_t bB = sb + A_BYTES + b_row_off;

#pragma unroll
        for (int ks = 0; ks < 4; ++ks) {
            const uint32_t acol = (uint32_t)(ks * 32 + a_cs16) ^ lxm;
            const uint32_t bcol = (uint32_t)(ks * 32 + b_cs16) ^ lxm;
            uint32_t afr[4][4];
#pragma unroll
            for (int mt = 0; mt < 4; ++mt)
                LDSM_X4(afr[mt][0], afr[mt][1], afr[mt][2], afr[mt][3],
                        aB + mt * 2048 + acol);
            uint32_t bfr[8][2];
#pragma unroll
            for (int j = 0; j < 4; ++j)
                LDSM_X4(bfr[2 * j][0], bfr[2 * j][1], bfr[2 * j + 1][0], bfr[2 * j + 1][1],
                        bB + j * 2048 + bcol);
#pragma unroll
            for (int mt = 0; mt < 4; ++mt)
#pragma unroll
                for (int nt = 0; nt < 8; ++nt)
                    mma16816(acc[mt][nt], afr[mt], bfr[nt][0], bfr[nt][1]);
        }

        if (i + 3 < NCHUNK) do_prefetch(i + 3);
        CP_COMMIT();
    }

    // ---- epilogue ----
#pragma unroll
    for (int mt = 0; mt < 4; ++mt) {
#pragma unroll
        for (int nt = 0; nt < 8; ++nt) {
            const int lc = wn * 64 + nt * 8 + tg * 2;
#pragma unroll
            for (int half = 0; half < 2; ++half) {
                const int r = i0 + wm * 64 + mt * 16 + grp + half * 8;
                if (r >= N) continue;
#pragma unroll
                for (int e = 0; e < 2; ++e) {
                    const float v = acc[mt][nt][half * 2 + e];
                    const int col = lc + e;
                    if (PASS == 1) {
                        if (col < 128) {
                            const float s = 1.f / (1.f + __expf(-(v + __ldg(&b0[col]))));
                            g_Z[(size_t)r * HID + col] = s;
                        } else {
                            const int cr = col - 128;
                            const float s = 1.f / (1.f + __expf(-(v + __ldg(&b1[cr]))));
                            g_RX[(size_t)r * CINL + cr] =
                                __float2half_rn(s * h[(size_t)r * HID + cr]);
                        }
                    } else {
                        const float q  = tanhf(v + __ldg(&b0[col]));
                        const float z  = g_Z[(size_t)r * HID + col];
                        const float hv = h[(size_t)r * HID + col];
                        out[(size_t)r * HID + col] = fmaf(z, q - hv, hv);
                    }
                }
            }
        }
    }
}

// ---------------- launch ----------------
extern "C" void kernel_launch(void* const* d_in, const int* in_sizes, int n_in,
                              void* d_out, int out_size) {
    const float* h     = (const float*)d_in[0];
    const float* x     = (const float*)d_in[1];
    const int*   nbr   = (const int*)  d_in[2];
    const float* Wz    = (const float*)d_in[3];
    const float* Wz_pt = (const float*)d_in[4];
    const float* bz    = (const float*)d_in[5];
    const float* Wr    = (const float*)d_in[6];
    const float* Wr_pt = (const float*)d_in[7];
    const float* br    = (const float*)d_in[8];
    const float* Wq    = (const float*)d_in[9];
    const float* Wq_pt = (const float*)d_in[10];
    const float* bq    = (const float*)d_in[11];

    const int N = in_sizes[0] / HID;
    const int SMEM = STAGES * 49152 + 128;   // 196736

    cudaFuncSetAttribute(sconv_mma<1, 2, 4>, cudaFuncAttributeMaxDynamicSharedMemorySize, SMEM);
    cudaFuncSetAttribute(sconv_mma<2, 4, 2>, cudaFuncAttributeMaxDynamicSharedMemorySize, SMEM);

    {
        size_t total = (size_t)N * CINL;
        pack_inputs<<<(unsigned)((total + 255) / 256), 256>>>(h, x, N);
    }
    {
        size_t total = (size_t)256 * KTOT;
        pack_wzr<<<(unsigned)((total + 255) / 256), 256>>>(Wz, Wz_pt, Wr, Wr_pt);
    }
    {
        size_t total = (size_t)128 * KTOT;
        pack_wq<<<(unsigned)((total + 255) / 256), 256>>>(Wq, Wq_pt);
    }

    sconv_mma<1, 2, 4><<<(N + 127) / 128, 256, SMEM>>>(nbr, h, bz, br, nullptr, N);
    sconv_mma<2, 4, 2><<<(N + 255) / 256, 256, SMEM>>>(nbr, h, bq, nullptr, (float*)d_out, N);
}

// round 6
// speedup vs baseline: 1.2469x; 1.2469x over previous
#include <cuda_runtime.h>
#include <cuda_fp16.h>
#include <cstdint>

#define NPT   120000
#define HID   128
#define INP   320
#define CINL  448
#define KOFF  28
#define KTOT  (KOFF * CINL)     // 12544
#define NCH   (KOFF * 14)       // 392 chunks of K=32
#define STAGES 8
#define A_BYTES 16384           // 256 rows x 64B
#define B_BYTES 8192            // 128 rows x 64B
#define STAGE_BYTES 24576

// ---------------- device scratch ----------------
__device__ __half g_HX [(size_t)NPT * CINL];
__device__ __half g_RX [(size_t)NPT * CINL];
__device__ float  g_Z  [(size_t)NPT * HID];
__device__ __half g_Wzr[(size_t)256 * KTOT];   // [n][k*448+c]  n<128: z, n>=128: r
__device__ __half g_Wq [(size_t)128 * KTOT];   // [n][k*448+c]

// ---------------- asm helpers ----------------
__device__ __forceinline__ uint32_t smem_u32(const void* p) {
    uint32_t a;
    asm("{ .reg .u64 t; cvta.to.shared.u64 t, %1; cvt.u32.u64 %0, t; }" : "=r"(a) : "l"(p));
    return a;
}
__device__ __forceinline__ void cp16(uint32_t dst, const void* src, int sz) {
    asm volatile("cp.async.cg.shared.global [%0], [%1], 16, %2;"
                 :: "r"(dst), "l"(src), "r"(sz) : "memory");
}
#define CP_COMMIT() asm volatile("cp.async.commit_group;" ::: "memory")
#define CP_WAIT0()  asm volatile("cp.async.wait_group 0;" ::: "memory")

#define LDSM_X4(r0, r1, r2, r3, addr) \
    asm volatile("ldmatrix.sync.aligned.m8n8.x4.shared.b16 {%0,%1,%2,%3}, [%4];" \
        : "=r"(r0), "=r"(r1), "=r"(r2), "=r"(r3) : "r"(addr))

__device__ __forceinline__ void mma16816(float* d, const uint32_t* a, uint32_t b0, uint32_t b1) {
    asm volatile(
        "mma.sync.aligned.m16n8k16.row.col.f32.f16.f16.f32 "
        "{%0,%1,%2,%3}, {%4,%5,%6,%7}, {%8,%9}, {%0,%1,%2,%3};"
        : "+f"(d[0]), "+f"(d[1]), "+f"(d[2]), "+f"(d[3])
        : "r"(a[0]), "r"(a[1]), "r"(a[2]), "r"(a[3]), "r"(b0), "r"(b1));
}

// 64B-row swizzle: seg' = (seg + (row>>1)) & 3   (16B segs, conflict-free LDSM)
__device__ __forceinline__ uint32_t sw64(int row, int seg) {
    return (uint32_t)(row * 64) + (uint32_t)(((seg + (row >> 1)) & 3) << 4);
}

// ---------------- packing kernels ----------------
__global__ void pack_inputs(const float* __restrict__ h, const float* __restrict__ x, int N) {
    size_t idx = (size_t)blockIdx.x * blockDim.x + threadIdx.x;
    size_t total = (size_t)N * CINL;
    if (idx >= total) return;
    int c = (int)(idx % CINL);
    size_t n = idx / CINL;
    float v = (c < HID) ? h[n * HID + c] : x[n * INP + (c - HID)];
    __half hv = __float2half_rn(v);
    g_HX[idx] = hv;
    if (c >= HID) g_RX[idx] = hv;
}

__global__ void pack_wzr(const float* __restrict__ Wz, const float* __restrict__ Wz_pt,
                         const float* __restrict__ Wr, const float* __restrict__ Wr_pt) {
    size_t idx = (size_t)blockIdx.x * blockDim.x + threadIdx.x;
    size_t total = (size_t)256 * KTOT;
    if (idx >= total) return;
    int rem = (int)(idx % KTOT);
    int n = (int)(idx / KTOT);
    int k = rem / CINL;
    int c = rem % CINL;
    float v;
    if (n < HID) v = (k < 27) ? Wz[((size_t)k * CINL + c) * HID + n] : Wz_pt[(size_t)c * HID + n];
    else {
        int m = n - HID;
        v = (k < 27) ? Wr[((size_t)k * CINL + c) * HID + m] : Wr_pt[(size_t)c * HID + m];
    }
    g_Wzr[idx] = __float2half_rn(v);
}

__global__ void pack_wq(const float* __restrict__ Wq, const float* __restrict__ Wq_pt) {
    size_t idx = (size_t)blockIdx.x * blockDim.x + threadIdx.x;
    size_t total = (size_t)128 * KTOT;
    if (idx >= total) return;
    int rem = (int)(idx % KTOT);
    int n = (int)(idx / KTOT);
    int k = rem / CINL;
    int c = rem % CINL;
    float v = (k < 27) ? Wq[((size_t)k * CINL + c) * HID + n] : Wq_pt[(size_t)c * HID + n];
    g_Wq[idx] = __float2half_rn(v);
}

// ---------------- main GEMM kernel ----------------
// BM=256, BN=128, BK=32. 16 warps = 4(M) x 4(N); warp tile 64x32.
// 8 stages, 4-chunk epochs: one wait_all + one barrier per epoch.
// PASS 1: A=g_HX, B=g_Wzr row-block ct*128 (ct=blockIdx.y: 0=z, 1=r)
// PASS 2: A=g_RX, B=g_Wq
template <int PASS>
__global__ void __launch_bounds__(512, 1)
sconv_mma(const int* __restrict__ nbr, const float* __restrict__ h,
          const float* __restrict__ b0, const float* __restrict__ b1,
          float* __restrict__ out, int N) {
    extern __shared__ __align__(128) char dynsmem[];

    const int tid  = threadIdx.x;
    const int wid  = tid >> 5;
    const int lane = tid & 31;
    const int wm   = wid >> 2;          // 0..3  (64 rows each)
    const int wn   = wid & 3;           // 0..3  (32 cols each)
    const int grp  = lane >> 2;
    const int tg   = lane & 3;
    const int i0   = blockIdx.x * 256;
    const int ct   = (PASS == 1) ? (int)blockIdx.y : 0;

    const __half* __restrict__ Asrc = (PASS == 1) ? g_HX : g_RX;
    const __half* __restrict__ WB   = (PASS == 1) ? g_Wzr : g_Wq;
    const size_t  nbase = (size_t)ct * 128;

    const uint32_t dsm_raw = smem_u32(dynsmem);
    const uint32_t dsm = (dsm_raw + 127u) & ~127u;

    // ---- prefetch constants ----
    // A: 256 rows x 4 segs of 16B = 1024 cp16 -> 2 per thread
    const int  arow  = tid >> 1;
    const int  aseg0 = (tid & 1) * 2;
    const int  g = i0 + arow;
    const uint32_t da0 = sw64(arow, aseg0);
    const uint32_t da1 = sw64(arow, aseg0 + 1);
    // B: 128 rows x 4 segs = 512 cp16 -> 1 per thread
    const int  brow  = tid >> 2;
    const int  bseg  = tid & 3;
    const uint32_t db0 = sw64(brow, bseg);
    const __half* pbrow = WB + (size_t)(nbase + brow) * KTOT;

    int    cur_k = -1;
    int    asz   = 0;
    size_t aoff  = 0;

    // ---- ldmatrix lane constants ----
    const int sel = lane >> 3;                      // 0..3
    const int l7  = lane & 7;
    // A: m0=rows0-7/k0-7, m1=rows8-15/k0-7, m2=rows0-7/k8-15, m3=rows8-15/k8-15
    uint32_t aa[4];
#pragma unroll
    for (int mt = 0; mt < 4; ++mt) {
        const int ar = wm * 64 + (sel & 1) * 8 + l7 + mt * 16;
        aa[mt] = sw64(ar, sel >> 1);                // seg0 for ks=0
    }
    // B: m0=rows0-7/k0-7, m1=rows0-7/k8-15, m2=rows8-15/k0-7, m3=rows8-15/k8-15
    uint32_t bb[2];
#pragma unroll
    for (int half = 0; half < 2; ++half) {
        const int br = wn * 32 + (sel >> 1) * 8 + l7 + half * 16;
        bb[half] = (uint32_t)A_BYTES + sw64(br, sel & 1);
    }

    float acc[4][4][4];
#pragma unroll
    for (int a = 0; a < 4; ++a)
#pragma unroll
        for (int b = 0; b < 4; ++b)
#pragma unroll
            for (int c = 0; c < 4; ++c) acc[a][b][c] = 0.f;

    // ---- prefetch one BK=32 chunk ----
    auto do_prefetch = [&](int j) {
        const int k  = j / 14;
        const int cc = (j % 14) * 32;
        const uint32_t sb = dsm + (j & (STAGES - 1)) * STAGE_BYTES;
        if (k != cur_k) {
            cur_k = k;
            int id = -1;
            if (g < N) id = (k == 27) ? g : nbr[(size_t)g * 27 + k];
            asz  = (id >= 0) ? 16 : 0;
            aoff = (size_t)((id >= 0) ? id : 0) * CINL;
        }
        const __half* pa = Asrc + aoff + cc + aseg0 * 8;
        cp16(sb + da0, pa,     asz);
        cp16(sb + da1, pa + 8, asz);
        cp16(sb + A_BYTES + db0, pbrow + (size_t)k * CINL + cc + bseg * 8, 16);
    };

    // ---- mma one BK=32 chunk ----
    auto do_mma = [&](int j) {
        const uint32_t sb = dsm + (j & (STAGES - 1)) * STAGE_BYTES;
#pragma unroll
        for (int ks = 0; ks < 2; ++ks) {
            const uint32_t kx = (uint32_t)(ks << 5);
            uint32_t bfr[4];
            LDSM_X4(bfr[0], bfr[1], bfr[2], bfr[3], (sb + bb[0]) ^ kx);
            uint32_t bfr2[4];
            LDSM_X4(bfr2[0], bfr2[1], bfr2[2], bfr2[3], (sb + bb[1]) ^ kx);
#pragma unroll
            for (int mt = 0; mt < 4; ++mt) {
                uint32_t afr[4];
                LDSM_X4(afr[0], afr[1], afr[2], afr[3], (sb + aa[mt]) ^ kx);
                mma16816(acc[mt][0], afr, bfr[0],  bfr[1]);
                mma16816(acc[mt][1], afr, bfr[2],  bfr[3]);
                mma16816(acc[mt][2], afr, bfr2[0], bfr2[1]);
                mma16816(acc[mt][3], afr, bfr2[2], bfr2[3]);
            }
        }
    };

    // initial fill: chunks 0..3 as one group
    do_prefetch(0); do_prefetch(1); do_prefetch(2); do_prefetch(3);
    CP_COMMIT();

    for (int i = 0; i < NCH; i += 4) {
        CP_WAIT0();
        __syncthreads();
        // prefetch next epoch (writes stages disjoint from this epoch's reads)
#pragma unroll
        for (int t = 0; t < 4; ++t) {
            const int j = i + 4 + t;
            if (j < NCH) do_prefetch(j);
        }
        CP_COMMIT();
        // compute this epoch
        do_mma(i); do_mma(i + 1); do_mma(i + 2); do_mma(i + 3);
    }

    // ---- epilogue ----
#pragma unroll
    for (int mt = 0; mt < 4; ++mt) {
#pragma unroll
        for (int nt = 0; nt < 4; ++nt) {
            const int lc = wn * 32 + nt * 8 + tg * 2;
#pragma unroll
            for (int half = 0; half < 2; ++half) {
                const int r = i0 + wm * 64 + mt * 16 + grp + half * 8;
                if (r >= N) continue;
#pragma unroll
                for (int e = 0; e < 2; ++e) {
                    const float v = acc[mt][nt][half * 2 + e];
                    const int col = lc + e;
                    if (PASS == 1) {
                        const float bias = (ct == 0) ? __ldg(&b0[col]) : __ldg(&b1[col]);
                        const float s = 1.f / (1.f + __expf(-(v + bias)));
                        if (ct == 0) g_Z[(size_t)r * HID + col] = s;
                        else g_RX[(size_t)r * CINL + col] =
                                 __float2half_rn(s * h[(size_t)r * HID + col]);
                    } else {
                        const float q  = tanhf(v + __ldg(&b0[col]));
                        const float z  = g_Z[(size_t)r * HID + col];
                        const float hv = h[(size_t)r * HID + col];
                        out[(size_t)r * HID + col] = fmaf(z, q - hv, hv);
                    }
                }
            }
        }
    }
}

// ---------------- launch ----------------
extern "C" void kernel_launch(void* const* d_in, const int* in_sizes, int n_in,
                              void* d_out, int out_size) {
    const float* h     = (const float*)d_in[0];
    const float* x     = (const float*)d_in[1];
    const int*   nbr   = (const int*)  d_in[2];
    const float* Wz    = (const float*)d_in[3];
    const float* Wz_pt = (const float*)d_in[4];
    const float* bz    = (const float*)d_in[5];
    const float* Wr    = (const float*)d_in[6];
    const float* Wr_pt = (const float*)d_in[7];
    const float* br    = (const float*)d_in[8];
    const float* Wq    = (const float*)d_in[9];
    const float* Wq_pt = (const float*)d_in[10];
    const float* bq    = (const float*)d_in[11];

    const int N = in_sizes[0] / HID;
    const int SMEM = STAGES * STAGE_BYTES + 128;   // 196736

    cudaFuncSetAttribute(sconv_mma<1>, cudaFuncAttributeMaxDynamicSharedMemorySize, SMEM);
    cudaFuncSetAttribute(sconv_mma<2>, cudaFuncAttributeMaxDynamicSharedMemorySize, SMEM);

    {
        size_t total = (size_t)N * CINL;
        pack_inputs<<<(unsigned)((total + 255) / 256), 256>>>(h, x, N);
    }
    {
        size_t total = (size_t)256 * KTOT;
        pack_wzr<<<(unsigned)((total + 255) / 256), 256>>>(Wz, Wz_pt, Wr, Wr_pt);
    }
    {
        size_t total = (size_t)128 * KTOT;
        pack_wq<<<(unsigned)((total + 255) / 256), 256>>>(Wq, Wq_pt);
    }

    dim3 g1((N + 255) / 256, 2);
    sconv_mma<1><<<g1, 512, SMEM>>>(nbr, h, bz, br, nullptr, N);

    dim3 g2((N + 255) / 256, 1);
    sconv_mma<2><<<g2, 512, SMEM>>>(nbr, h, bq, nullptr, (float*)d_out, N);
}

// round 7
// speedup vs baseline: 1.2509x; 1.0032x over previous
#include <cuda_runtime.h>
#include <cuda_fp16.h>
#include <cstdint>

#define NPT   120000
#define HID   128
#define INP   320
#define CINL  448
#define KOFF  28
#define KTOT  (KOFF * CINL)     // 12544
#define NCHUNK (KOFF * 7)       // 196 chunks of K=64
#define STAGES 4
#define BM    192
#define A_BYTES (BM * 128)      // 24576
#define B_BYTES 16384           // 128 rows x 128B
#define STAGE_BYTES (A_BYTES + B_BYTES)   // 40960

// ---------------- device scratch ----------------
__device__ __half g_HX [(size_t)NPT * CINL];
__device__ __half g_RX [(size_t)NPT * CINL];
__device__ float  g_Z  [(size_t)NPT * HID];
__device__ __half g_Wzr[(size_t)256 * KTOT];   // [n][k*448+c]  n<128: z, n>=128: r
__device__ __half g_Wq [(size_t)128 * KTOT];   // [n][k*448+c]

// ---------------- asm helpers ----------------
__device__ __forceinline__ uint32_t smem_u32(const void* p) {
    uint32_t a;
    asm("{ .reg .u64 t; cvta.to.shared.u64 t, %1; cvt.u32.u64 %0, t; }" : "=r"(a) : "l"(p));
    return a;
}
__device__ __forceinline__ void cp16(uint32_t dst, const void* src, int sz) {
    asm volatile("cp.async.cg.shared.global [%0], [%1], 16, %2;"
                 :: "r"(dst), "l"(src), "r"(sz) : "memory");
}
#define CP_COMMIT() asm volatile("cp.async.commit_group;" ::: "memory")
#define CP_WAIT2()  asm volatile("cp.async.wait_group 2;" ::: "memory")

#define LDSM_X4(r0, r1, r2, r3, addr) \
    asm volatile("ldmatrix.sync.aligned.m8n8.x4.shared.b16 {%0,%1,%2,%3}, [%4];" \
        : "=r"(r0), "=r"(r1), "=r"(r2), "=r"(r3) : "r"(addr))

__device__ __forceinline__ void mma16816(float* d, const uint32_t* a, uint32_t b0, uint32_t b1) {
    asm volatile(
        "mma.sync.aligned.m16n8k16.row.col.f32.f16.f16.f32 "
        "{%0,%1,%2,%3}, {%4,%5,%6,%7}, {%8,%9}, {%0,%1,%2,%3};"
        : "+f"(d[0]), "+f"(d[1]), "+f"(d[2]), "+f"(d[3])
        : "r"(a[0]), "r"(a[1]), "r"(a[2]), "r"(a[3]), "r"(b0), "r"(b1));
}

// ---------------- packing kernels ----------------
__global__ void pack_inputs(const float* __restrict__ h, const float* __restrict__ x, int N) {
    size_t idx = (size_t)blockIdx.x * blockDim.x + threadIdx.x;
    size_t total = (size_t)N * CINL;
    if (idx >= total) return;
    int c = (int)(idx % CINL);
    size_t n = idx / CINL;
    float v = (c < HID) ? h[n * HID + c] : x[n * INP + (c - HID)];
    __half hv = __float2half_rn(v);
    g_HX[idx] = hv;
    if (c >= HID) g_RX[idx] = hv;
}

__global__ void pack_wzr(const float* __restrict__ Wz, const float* __restrict__ Wz_pt,
                         const float* __restrict__ Wr, const float* __restrict__ Wr_pt) {
    size_t idx = (size_t)blockIdx.x * blockDim.x + threadIdx.x;
    size_t total = (size_t)256 * KTOT;
    if (idx >= total) return;
    int rem = (int)(idx % KTOT);
    int n = (int)(idx / KTOT);
    int k = rem / CINL;
    int c = rem % CINL;
    float v;
    if (n < HID) v = (k < 27) ? Wz[((size_t)k * CINL + c) * HID + n] : Wz_pt[(size_t)c * HID + n];
    else {
        int m = n - HID;
        v = (k < 27) ? Wr[((size_t)k * CINL + c) * HID + m] : Wr_pt[(size_t)c * HID + m];
    }
    g_Wzr[idx] = __float2half_rn(v);
}

__global__ void pack_wq(const float* __restrict__ Wq, const float* __restrict__ Wq_pt) {
    size_t idx = (size_t)blockIdx.x * blockDim.x + threadIdx.x;
    size_t total = (size_t)128 * KTOT;
    if (idx >= total) return;
    int rem = (int)(idx % KTOT);
    int n = (int)(idx / KTOT);
    int k = rem / CINL;
    int c = rem % CINL;
    float v = (k < 27) ? Wq[((size_t)k * CINL + c) * HID + n] : Wq_pt[(size_t)c * HID + n];
    g_Wq[idx] = __float2half_rn(v);
}

// ---------------- main GEMM kernel ----------------
// BM=192, BN=128, BK=64. 12 warps = 3(M) x 4(N); warp tile 64x32.
// Explicit ks software pipeline with double-buffered fragments.
// PASS 1: A=g_HX, B=g_Wzr row-block ct*128 (ct=blockIdx.y: 0=z, 1=r)
// PASS 2: A=g_RX, B=g_Wq
template <int PASS>
__global__ void __launch_bounds__(384, 1)
sconv_mma(const int* __restrict__ nbr, const float* __restrict__ h,
          const float* __restrict__ b0, const float* __restrict__ b1,
          float* __restrict__ out, int N) {
    extern __shared__ __align__(128) char dynsmem[];

    const int tid  = threadIdx.x;
    const int wid  = tid >> 5;
    const int lane = tid & 31;
    const int wm   = wid >> 2;          // 0..2  (64 rows each)
    const int wn   = wid & 3;           // 0..3  (32 cols each)
    const int grp  = lane >> 2;
    const int tg   = lane & 3;
    const int i0   = blockIdx.x * BM;
    const int ct   = (PASS == 1) ? (int)blockIdx.y : 0;

    const __half* __restrict__ Asrc = (PASS == 1) ? g_HX : g_RX;
    const __half* __restrict__ WB   = (PASS == 1) ? g_Wzr : g_Wq;
    const size_t  nbase = (size_t)ct * 128;

    const uint32_t dsm_raw = smem_u32(dynsmem);
    const uint32_t dsm = (dsm_raw + 127u) & ~127u;

    // ---- prefetch constants ----
    // A: 192 rows x 8 segs of 16B = 1536 cp16 -> 4 per thread (384 thr)
    const int  arow  = tid >> 1;
    const int  aseg0 = (tid & 1) * 4;
    const uint32_t axm = (uint32_t)((arow & 7) << 4);
    const int  g = i0 + arow;

    int    cur_k = -1;
    int    asz   = 0;
    size_t aoff  = 0;

    // ---- ldmatrix lane constants ----
    const int sel = lane >> 3;                      // 0..3
    const uint32_t lxm = (uint32_t)((lane & 7) << 4);
    const uint32_t a_row_off =
        (uint32_t)(wm * 64 + (sel & 1) * 8 + (lane & 7)) * 128;
    const uint32_t a_cs16 = (uint32_t)((sel >> 1) * 16);
    const uint32_t b_row_off =
        (uint32_t)(wn * 32 + (sel >> 1) * 8 + (lane & 7)) * 128;
    const uint32_t b_cs16 = (uint32_t)((sel & 1) * 16);

    float acc[4][4][4];
#pragma unroll
    for (int a = 0; a < 4; ++a)
#pragma unroll
        for (int b = 0; b < 4; ++b)
#pragma unroll
            for (int c = 0; c < 4; ++c) acc[a][b][c] = 0.f;

    // ---- prefetch one BK=64 chunk ----
    auto do_prefetch = [&](int j) {
        const int k  = j / 7;
        const int cc = (j % 7) * 64;
        const int s  = j & (STAGES - 1);
        if (k != cur_k) {
            cur_k = k;
            int id = -1;
            if (g < N) id = (k == 27) ? g : nbr[(size_t)g * 27 + k];
            asz  = (id >= 0) ? 16 : 0;
            aoff = (size_t)((id >= 0) ? id : 0) * CINL;
        }
        const uint32_t sb = dsm + s * STAGE_BYTES;
        const __half* pa = Asrc + aoff + cc + aseg0 * 8;
        const uint32_t da = sb + (uint32_t)arow * 128;
#pragma unroll
        for (int t = 0; t < 4; ++t) {
            const uint32_t so = (uint32_t)((aseg0 + t) * 16) ^ axm;
            cp16(da + so, pa + t * 8, asz);
        }
        // B: 128 rows x 8 segs = 1024 cp16 over 384 threads (3 strided iters)
        const size_t kbase = (size_t)k * CINL + cc;
        for (int j2 = tid; j2 < 1024; j2 += 384) {
            const int row = j2 >> 3;
            const int seg = j2 & 7;
            const uint32_t so = (uint32_t)(seg * 16) ^ (uint32_t)((row & 7) << 4);
            cp16(sb + A_BYTES + (uint32_t)row * 128 + so,
                 WB + (size_t)(nbase + row) * KTOT + kbase + seg * 8, 16);
        }
    };

    do_prefetch(0); CP_COMMIT();
    do_prefetch(1); CP_COMMIT();
    do_prefetch(2); CP_COMMIT();

    for (int i = 0; i < NCHUNK; ++i) {
        CP_WAIT2();
        __syncthreads();

        if (i + 3 < NCHUNK) do_prefetch(i + 3);
        CP_COMMIT();

        const uint32_t sb = dsm + (i & (STAGES - 1)) * STAGE_BYTES;
        const uint32_t aB = sb + a_row_off;
        const uint32_t bB = sb + A_BYTES + b_row_off;

        // double-buffered fragments, ks software pipeline
        uint32_t afr[2][4][4];
        uint32_t bfr[2][2][4];

        // preload ks = 0 into buffer 0
        {
            const uint32_t acol = a_cs16 ^ lxm;
            const uint32_t bcol = b_cs16 ^ lxm;
            LDSM_X4(bfr[0][0][0], bfr[0][0][1], bfr[0][0][2], bfr[0][0][3], bB + bcol);
            LDSM_X4(bfr[0][1][0], bfr[0][1][1], bfr[0][1][2], bfr[0][1][3], bB + 2048 + bcol);
#pragma unroll
            for (int mt = 0; mt < 4; ++mt)
                LDSM_X4(afr[0][mt][0], afr[0][mt][1], afr[0][mt][2], afr[0][mt][3],
                        aB + mt * 2048 + acol);
        }

#pragma unroll
        for (int ks = 0; ks < 4; ++ks) {
            const int cur = ks & 1;
            const int nxt = cur ^ 1;
            if (ks < 3) {
                const uint32_t acol = (uint32_t)((ks + 1) * 32 + a_cs16) ^ lxm;
                const uint32_t bcol = (uint32_t)((ks + 1) * 32 + b_cs16) ^ lxm;
                LDSM_X4(bfr[nxt][0][0], bfr[nxt][0][1], bfr[nxt][0][2], bfr[nxt][0][3],
                        bB + bcol);
                LDSM_X4(bfr[nxt][1][0], bfr[nxt][1][1], bfr[nxt][1][2], bfr[nxt][1][3],
                        bB + 2048 + bcol);
#pragma unroll
                for (int mt = 0; mt < 4; ++mt)
                    LDSM_X4(afr[nxt][mt][0], afr[nxt][mt][1], afr[nxt][mt][2], afr[nxt][mt][3],
                            aB + mt * 2048 + acol);
            }
#pragma unroll
            for (int mt = 0; mt < 4; ++mt) {
#pragma unroll
                for (int p = 0; p < 2; ++p) {
                    mma16816(acc[mt][2 * p],     afr[cur][mt], bfr[cur][p][0], bfr[cur][p][1]);
                    mma16816(acc[mt][2 * p + 1], afr[cur][mt], bfr[cur][p][2], bfr[cur][p][3]);
                }
            }
        }
    }

    // ---- epilogue ----
#pragma unroll
    for (int mt = 0; mt < 4; ++mt) {
#pragma unroll
        for (int nt = 0; nt < 4; ++nt) {
            const int lc = wn * 32 + nt * 8 + tg * 2;
#pragma unroll
            for (int half = 0; half < 2; ++half) {
                const int r = i0 + wm * 64 + mt * 16 + grp + half * 8;
                if (r >= N) continue;
#pragma unroll
                for (int e = 0; e < 2; ++e) {
                    const float v = acc[mt][nt][half * 2 + e];
                    const int col = lc + e;
                    if (PASS == 1) {
                        const float bias = (ct == 0) ? __ldg(&b0[col]) : __ldg(&b1[col]);
                        const float s = 1.f / (1.f + __expf(-(v + bias)));
                        if (ct == 0) g_Z[(size_t)r * HID + col] = s;
                        else g_RX[(size_t)r * CINL + col] =
                                 __float2half_rn(s * h[(size_t)r * HID + col]);
                    } else {
                        const float q  = tanhf(v + __ldg(&b0[col]));
                        const float z  = g_Z[(size_t)r * HID + col];
                        const float hv = h[(size_t)r * HID + col];
                        out[(size_t)r * HID + col] = fmaf(z, q - hv, hv);
                    }
                }
            }
        }
    }
}

// ---------------- launch ----------------
extern "C" void kernel_launch(void* const* d_in, const int* in_sizes, int n_in,
                              void* d_out, int out_size) {
    const float* h     = (const float*)d_in[0];
    const float* x     = (const float*)d_in[1];
    const int*   nbr   = (const int*)  d_in[2];
    const float* Wz    = (const float*)d_in[3];
    const float* Wz_pt = (const float*)d_in[4];
    const float* bz    = (const float*)d_in[5];
    const float* Wr    = (const float*)d_in[6];
    const float* Wr_pt = (const float*)d_in[7];
    const float* br    = (const float*)d_in[8];
    const float* Wq    = (const float*)d_in[9];
    const float* Wq_pt = (const float*)d_in[10];
    const float* bq    = (const float*)d_in[11];

    const int N = in_sizes[0] / HID;
    const int SMEM = STAGES * STAGE_BYTES + 128;   // 163968

    cudaFuncSetAttribute(sconv_mma<1>, cudaFuncAttributeMaxDynamicSharedMemorySize, SMEM);
    cudaFuncSetAttribute(sconv_mma<2>, cudaFuncAttributeMaxDynamicSharedMemorySize, SMEM);

    {
        size_t total = (size_t)N * CINL;
        pack_inputs<<<(unsigned)((total + 255) / 256), 256>>>(h, x, N);
    }
    {
        size_t total = (size_t)256 * KTOT;
        pack_wzr<<<(unsigned)((total + 255) / 256), 256>>>(Wz, Wz_pt, Wr, Wr_pt);
    }
    {
        size_t total = (size_t)128 * KTOT;
        pack_wq<<<(unsigned)((total + 255) / 256), 256>>>(Wq, Wq_pt);
    }

    dim3 g1((N + BM - 1) / BM, 2);
    sconv_mma<1><<<g1, 384, SMEM>>>(nbr, h, bz, br, nullptr, N);

    dim3 g2((N + BM - 1) / BM, 1);
    sconv_mma<2><<<g2, 384, SMEM>>>(nbr, h, bq, nullptr, (float*)d_out, N);
}

// round 8
// speedup vs baseline: 1.2532x; 1.0018x over previous
#include <cuda_runtime.h>
#include <cuda_fp16.h>
#include <cstdint>

#define NPT   120000
#define HID   128
#define INP   320
#define CINL  448
#define KOFF  28
#define KTOT  (KOFF * CINL)     // 12544
#define NCHUNK (KOFF * 7)       // 196 chunks of K=64
#define STAGES 4
#define A_BYTES 32768           // 256 rows x 128B
#define B_BYTES 16384           // 128 rows x 128B (one pre-swizzled chunk block)
#define STAGE_BYTES (A_BYTES + B_BYTES)   // 49152
#define B_CHUNK_HALVES (128 * 64)         // 8192 halves = 16KB

// ---------------- device scratch ----------------
__device__ __half g_HX [(size_t)NPT * CINL];
__device__ __half g_RX [(size_t)NPT * CINL];
__device__ float  g_Z  [(size_t)NPT * HID];
// chunk-major, pre-swizzled weights: [ct][chunk][row 0..127][64 halves (swizzled)]
__device__ __half g_Wzr2[(size_t)2 * NCHUNK * B_CHUNK_HALVES];
__device__ __half g_Wq2 [(size_t)NCHUNK * B_CHUNK_HALVES];

// ---------------- asm helpers ----------------
__device__ __forceinline__ uint32_t smem_u32(const void* p) {
    uint32_t a;
    asm("{ .reg .u64 t; cvta.to.shared.u64 t, %1; cvt.u32.u64 %0, t; }" : "=r"(a) : "l"(p));
    return a;
}
__device__ __forceinline__ void cp16(uint32_t dst, const void* src, int sz) {
    asm volatile("cp.async.cg.shared.global [%0], [%1], 16, %2;"
                 :: "r"(dst), "l"(src), "r"(sz) : "memory");
}
#define CP_COMMIT() asm volatile("cp.async.commit_group;" ::: "memory")
#define CP_WAIT2()  asm volatile("cp.async.wait_group 2;" ::: "memory")

#define MBARRIER_INIT(addr, cnt) \
    asm volatile("mbarrier.init.shared.b64 [%0], %1;" :: "r"(addr), "r"(cnt) : "memory")
#define MBARRIER_EXPECT_TX(addr, tx) \
    asm volatile("mbarrier.arrive.expect_tx.shared.b64 _, [%0], %1;" \
        :: "r"(addr), "r"(tx) : "memory")
#define MBARRIER_WAIT_PARITY(addr, par) do { \
    uint32_t _m = (addr); uint32_t _p = (par); uint32_t _done; \
    asm volatile("{\n\t.reg .pred p;\n\t" \
        "mbarrier.try_wait.parity.acquire.cta.shared::cta.b64 p, [%1], %2;\n\t" \
        "selp.b32 %0, 1, 0, p;\n\t}" : "=r"(_done) : "r"(_m), "r"(_p) : "memory"); \
    if (!_done) { \
        asm volatile("{\n\t.reg .pred P1;\n\t" \
            "WL_%=:\n\t" \
            "mbarrier.try_wait.parity.acquire.cta.shared::cta.b64 P1, [%0], %1, 0x989680;\n\t" \
            "@P1 bra.uni WD_%=;\n\t" \
            "bra.uni WL_%=;\n\t" \
            "WD_%=:\n\t}" :: "r"(_m), "r"(_p) : "memory"); \
    } \
} while (0)

__device__ __forceinline__ void bulk_ld(uint32_t dst, const void* src, int bytes, uint32_t mbar) {
    asm volatile(
        "cp.async.bulk.shared::cluster.global.mbarrier::complete_tx::bytes [%0], [%1], %2, [%3];"
        :: "r"(dst), "l"(src), "r"(bytes), "r"(mbar) : "memory");
}

#define LDSM_X4(r0, r1, r2, r3, addr) \
    asm volatile("ldmatrix.sync.aligned.m8n8.x4.shared.b16 {%0,%1,%2,%3}, [%4];" \
        : "=r"(r0), "=r"(r1), "=r"(r2), "=r"(r3) : "r"(addr))

__device__ __forceinline__ void mma16816(float* d, const uint32_t* a, uint32_t b0, uint32_t b1) {
    asm volatile(
        "mma.sync.aligned.m16n8k16.row.col.f32.f16.f16.f32 "
        "{%0,%1,%2,%3}, {%4,%5,%6,%7}, {%8,%9}, {%0,%1,%2,%3};"
        : "+f"(d[0]), "+f"(d[1]), "+f"(d[2]), "+f"(d[3])
        : "r"(a[0]), "r"(a[1]), "r"(a[2]), "r"(a[3]), "r"(b0), "r"(b1));
}

// ---------------- packing kernels ----------------
__global__ void pack_inputs(const float* __restrict__ h, const float* __restrict__ x, int N) {
    size_t idx = (size_t)blockIdx.x * blockDim.x + threadIdx.x;
    size_t total = (size_t)N * CINL;
    if (idx >= total) return;
    int c = (int)(idx % CINL);
    size_t n = idx / CINL;
    float v = (c < HID) ? h[n * HID + c] : x[n * INP + (c - HID)];
    __half hv = __float2half_rn(v);
    g_HX[idx] = hv;
    if (c >= HID) g_RX[idx] = hv;
}

// target half index inside a chunk block for output-col row, input-col c64
__device__ __forceinline__ size_t bsw(int row, int c64) {
    int seg = c64 >> 3;
    int e   = c64 & 7;
    return (size_t)row * 64 + (size_t)((seg ^ (row & 7)) * 8 + e);
}

__global__ void pack_wzr(const float* __restrict__ Wz, const float* __restrict__ Wz_pt,
                         const float* __restrict__ Wr, const float* __restrict__ Wr_pt) {
    size_t idx = (size_t)blockIdx.x * blockDim.x + threadIdx.x;
    size_t total = (size_t)256 * KTOT;
    if (idx >= total) return;
    int rem = (int)(idx % KTOT);
    int n = (int)(idx / KTOT);          // 0..255
    int k = rem / CINL;
    int c = rem % CINL;
    float v;
    if (n < HID) v = (k < 27) ? Wz[((size_t)k * CINL + c) * HID + n] : Wz_pt[(size_t)c * HID + n];
    else {
        int m = n - HID;
        v = (k < 27) ? Wr[((size_t)k * CINL + c) * HID + m] : Wr_pt[(size_t)c * HID + m];
    }
    const int ct  = n >> 7;
    const int row = n & 127;
    const int j   = k * 7 + (c >> 6);
    g_Wzr2[(size_t)(ct * NCHUNK + j) * B_CHUNK_HALVES + bsw(row, c & 63)] = __float2half_rn(v);
}

__global__ void pack_wq(const float* __restrict__ Wq, const float* __restrict__ Wq_pt) {
    size_t idx = (size_t)blockIdx.x * blockDim.x + threadIdx.x;
    size_t total = (size_t)128 * KTOT;
    if (idx >= total) return;
    int rem = (int)(idx % KTOT);
    int n = (int)(idx / KTOT);
    int k = rem / CINL;
    int c = rem % CINL;
    float v = (k < 27) ? Wq[((size_t)k * CINL + c) * HID + n] : Wq_pt[(size_t)c * HID + n];
    const int j = k * 7 + (c >> 6);
    g_Wq2[(size_t)j * B_CHUNK_HALVES + bsw(n, c & 63)] = __float2half_rn(v);
}

// ---------------- main GEMM kernel ----------------
// BM=256, BN=128, BK=64. 16 warps = 4(M) x 4(N); warp tile 64x32.
// A via cp.async (gather, zfill); B via cp.async.bulk of pre-swizzled 16KB blocks.
// Warp ks de-phasing: rotate ks order by (wid>>2)&3.
// PASS 1: A=g_HX, B=g_Wzr2[ct] (ct=blockIdx.y: 0=z, 1=r)
// PASS 2: A=g_RX, B=g_Wq2
template <int PASS>
__global__ void __launch_bounds__(512, 1)
sconv_mma(const int* __restrict__ nbr, const float* __restrict__ h,
          const float* __restrict__ b0, const float* __restrict__ b1,
          float* __restrict__ out, int N) {
    extern __shared__ __align__(128) char dynsmem[];
    __shared__ __align__(8) uint64_t s_mbar[STAGES];

    const int tid  = threadIdx.x;
    const int wid  = tid >> 5;
    const int lane = tid & 31;
    const int wm   = wid >> 2;          // 0..3  (64 rows each)
    const int wn   = wid & 3;           // 0..3  (32 cols each)
    const int grp  = lane >> 2;
    const int tg   = lane & 3;
    const int i0   = blockIdx.x * 256;
    const int ct   = (PASS == 1) ? (int)blockIdx.y : 0;

    const __half* __restrict__ Asrc = (PASS == 1) ? g_HX : g_RX;
    const __half* __restrict__ WB2  = (PASS == 1)
        ? (g_Wzr2 + (size_t)ct * NCHUNK * B_CHUNK_HALVES) : g_Wq2;

    const uint32_t dsm_raw = smem_u32(dynsmem);
    const uint32_t dsm = (dsm_raw + 127u) & ~127u;

    uint32_t mbar[STAGES];
#pragma unroll
    for (int s = 0; s < STAGES; ++s) mbar[s] = smem_u32(&s_mbar[s]);

    if (tid == 0) {
#pragma unroll
        for (int s = 0; s < STAGES; ++s) MBARRIER_INIT(mbar[s], 1);
        asm volatile("fence.mbarrier_init.release.cluster;" ::: "memory");
    }
    __syncthreads();

    // ---- prefetch constants ----
    const int  arow  = tid >> 1;              // 0..255
    const int  aseg0 = (tid & 1) * 4;
    const uint32_t axm = (uint32_t)((arow & 7) << 4);
    const int  g = i0 + arow;

    int    cur_k = -1;
    int    asz   = 0;
    size_t aoff  = 0;

    // ---- ldmatrix lane constants ----
    const int sel = lane >> 3;                      // 0..3
    const uint32_t lxm = (uint32_t)((lane & 7) << 4);
    const uint32_t a_row_off =
        (uint32_t)(wm * 64 + (sel & 1) * 8 + (lane & 7)) * 128;
    const uint32_t a_cs16 = (uint32_t)((sel >> 1) * 16);
    const uint32_t b_row_off =
        (uint32_t)(wn * 32 + (sel >> 1) * 8 + (lane & 7)) * 128;
    const uint32_t b_cs16 = (uint32_t)((sel & 1) * 16);
    const int krot = (wid >> 2) & 3;                // per-SMSP warp de-phasing

    float acc[4][4][4];
#pragma unroll
    for (int a = 0; a < 4; ++a)
#pragma unroll
        for (int b = 0; b < 4; ++b)
#pragma unroll
            for (int c = 0; c < 4; ++c) acc[a][b][c] = 0.f;

    // ---- prefetch A (cp.async) for chunk j ----
    auto do_pref_a = [&](int j) {
        const int k  = j / 7;
        const int cc = (j % 7) * 64;
        const int s  = j & (STAGES - 1);
        if (k != cur_k) {
            cur_k = k;
            int id = -1;
            if (g < N) id = (k == 27) ? g : nbr[(size_t)g * 27 + k];
            asz  = (id >= 0) ? 16 : 0;
            aoff = (size_t)((id >= 0) ? id : 0) * CINL;
        }
        const __half* pa = Asrc + aoff + cc + aseg0 * 8;
        const uint32_t da = dsm + s * STAGE_BYTES + (uint32_t)arow * 128;
#pragma unroll
        for (int t = 0; t < 4; ++t) {
            const uint32_t so = (uint32_t)((aseg0 + t) * 16) ^ axm;
            cp16(da + so, pa + t * 8, asz);
        }
    };
    // ---- prefetch B (bulk) for chunk j ----
    auto do_pref_b = [&](int j) {
        if (tid == 0) {
            const int s = j & (STAGES - 1);
            MBARRIER_EXPECT_TX(mbar[s], B_BYTES);
            bulk_ld(dsm + s * STAGE_BYTES + A_BYTES,
                    WB2 + (size_t)j * B_CHUNK_HALVES, B_BYTES, mbar[s]);
        }
    };

    do_pref_a(0); CP_COMMIT(); do_pref_b(0);
    do_pref_a(1); CP_COMMIT(); do_pref_b(1);
    do_pref_a(2); CP_COMMIT(); do_pref_b(2);

    for (int i = 0; i < NCHUNK; ++i) {
        CP_WAIT2();
        MBARRIER_WAIT_PARITY(mbar[i & (STAGES - 1)], (i >> 2) & 1);
        __syncthreads();

        if (i + 3 < NCHUNK) { do_pref_a(i + 3); do_pref_b(i + 3); }
        CP_COMMIT();

        const uint32_t sb = dsm + (i & (STAGES - 1)) * STAGE_BYTES;
        const uint32_t aB = sb + a_row_off;
        const uint32_t bB = sb + A_BYTES + b_row_off;

#pragma unroll
        for (int kk = 0; kk < 4; ++kk) {
            const int ks = (kk + krot) & 3;
            const uint32_t acol = (uint32_t)(ks * 32 + a_cs16) ^ lxm;
            const uint32_t bcol = (uint32_t)(ks * 32 + b_cs16) ^ lxm;
            uint32_t bfr[2][4];
            LDSM_X4(bfr[0][0], bfr[0][1], bfr[0][2], bfr[0][3], bB + bcol);
            LDSM_X4(bfr[1][0], bfr[1][1], bfr[1][2], bfr[1][3], bB + 2048 + bcol);
#pragma unroll
            for (int mt = 0; mt < 4; ++mt) {
                uint32_t afr[4];
                LDSM_X4(afr[0], afr[1], afr[2], afr[3], aB + mt * 2048 + acol);
#pragma unroll
                for (int p = 0; p < 2; ++p) {
                    mma16816(acc[mt][2 * p],     afr, bfr[p][0], bfr[p][1]);
                    mma16816(acc[mt][2 * p + 1], afr, bfr[p][2], bfr[p][3]);
                }
            }
        }
    }

    // ---- epilogue ----
#pragma unroll
    for (int mt = 0; mt < 4; ++mt) {
#pragma unroll
        for (int nt = 0; nt < 4; ++nt) {
            const int lc = wn * 32 + nt * 8 + tg * 2;
#pragma unroll
            for (int half = 0; half < 2; ++half) {
                const int r = i0 + wm * 64 + mt * 16 + grp + half * 8;
                if (r >= N) continue;
#pragma unroll
                for (int e = 0; e < 2; ++e) {
                    const float v = acc[mt][nt][half * 2 + e];
                    const int col = lc + e;
                    if (PASS == 1) {
                        const float bias = (ct == 0) ? __ldg(&b0[col]) : __ldg(&b1[col]);
                        const float s = 1.f / (1.f + __expf(-(v + bias)));
                        if (ct == 0) g_Z[(size_t)r * HID + col] = s;
                        else g_RX[(size_t)r * CINL + col] =
                                 __float2half_rn(s * h[(size_t)r * HID + col]);
                    } else {
                        const float q  = tanhf(v + __ldg(&b0[col]));
                        const float z  = g_Z[(size_t)r * HID + col];
                        const float hv = h[(size_t)r * HID + col];
                        out[(size_t)r * HID + col] = fmaf(z, q - hv, hv);
                    }
                }
            }
        }
    }
}

// ---------------- launch ----------------
extern "C" void kernel_launch(void* const* d_in, const int* in_sizes, int n_in,
                              void* d_out, int out_size) {
    const float* h     = (const float*)d_in[0];
    const float* x     = (const float*)d_in[1];
    const int*   nbr   = (const int*)  d_in[2];
    const float* Wz    = (const float*)d_in[3];
    const float* Wz_pt = (const float*)d_in[4];
    const float* bz    = (const float*)d_in[5];
    const float* Wr    = (const float*)d_in[6];
    const float* Wr_pt = (const float*)d_in[7];
    const float* br    = (const float*)d_in[8];
    const float* Wq    = (const float*)d_in[9];
    const float* Wq_pt = (const float*)d_in[10];
    const float* bq    = (const float*)d_in[11];

    const int N = in_sizes[0] / HID;
    const int SMEM = STAGES * STAGE_BYTES + 128;   // 196736

    cudaFuncSetAttribute(sconv_mma<1>, cudaFuncAttributeMaxDynamicSharedMemorySize, SMEM);
    cudaFuncSetAttribute(sconv_mma<2>, cudaFuncAttributeMaxDynamicSharedMemorySize, SMEM);

    {
        size_t total = (size_t)N * CINL;
        pack_inputs<<<(unsigned)((total + 255) / 256), 256>>>(h, x, N);
    }
    {
        size_t total = (size_t)256 * KTOT;
        pack_wzr<<<(unsigned)((total + 255) / 256), 256>>>(Wz, Wz_pt, Wr, Wr_pt);
    }
    {
        size_t total = (size_t)128 * KTOT;
        pack_wq<<<(unsigned)((total + 255) / 256), 256>>>(Wq, Wq_pt);
    }

    dim3 g1((N + 255) / 256, 2);
    sconv_mma<1><<<g1, 512, SMEM>>>(nbr, h, bz, br, nullptr, N);

    dim3 g2((N + 255) / 256, 1);
    sconv_mma<2><<<g2, 512, SMEM>>>(nbr, h, bq, nullptr, (float*)d_out, N);
}

// round 9
// speedup vs baseline: 1.8433x; 1.4709x over previous
#include <cuda_runtime.h>
#include <cuda_fp16.h>
#include <cstdint>

#define NPT   120000
#define HID   128
#define INP   320
#define CINL  448
#define KOFF  28
#define KTOT  (KOFF * CINL)     // 12544

// ---------------- device scratch ----------------
__device__ __half g_HX [(size_t)NPT * CINL];
__device__ __half g_RX [(size_t)NPT * CINL];
__device__ float  g_Z  [(size_t)NPT * HID];
__device__ __half g_Wzr[(size_t)256 * KTOT];   // [n][k*448+c]  n<128: z, n>=128: r
__device__ __half g_Wq [(size_t)128 * KTOT];   // [n][k*448+c]
// G buffer: pass1 uses [28][NPT][256] halves; pass2 reuses as [28][NPT][128]
__device__ __half g_G  [(size_t)KOFF * NPT * 256];
__device__ int    g_list[(size_t)27 * NPT];
__device__ int    g_cnt[27];

// ---------------- asm helpers ----------------
__device__ __forceinline__ uint32_t smem_u32(const void* p) {
    uint32_t a;
    asm("{ .reg .u64 t; cvta.to.shared.u64 t, %1; cvt.u32.u64 %0, t; }" : "=r"(a) : "l"(p));
    return a;
}
__device__ __forceinline__ void cp16(uint32_t dst, const void* src, int sz) {
    asm volatile("cp.async.cg.shared.global [%0], [%1], 16, %2;"
                 :: "r"(dst), "l"(src), "r"(sz) : "memory");
}
#define CP_COMMIT() asm volatile("cp.async.commit_group;" ::: "memory")
#define CP_WAIT2()  asm volatile("cp.async.wait_group 2;" ::: "memory")

#define LDSM_X4(r0, r1, r2, r3, addr) \
    asm volatile("ldmatrix.sync.aligned.m8n8.x4.shared.b16 {%0,%1,%2,%3}, [%4];" \
        : "=r"(r0), "=r"(r1), "=r"(r2), "=r"(r3) : "r"(addr))

__device__ __forceinline__ void mma16816(float* d, const uint32_t* a, uint32_t b0, uint32_t b1) {
    asm volatile(
        "mma.sync.aligned.m16n8k16.row.col.f32.f16.f16.f32 "
        "{%0,%1,%2,%3}, {%4,%5,%6,%7}, {%8,%9}, {%0,%1,%2,%3};"
        : "+f"(d[0]), "+f"(d[1]), "+f"(d[2]), "+f"(d[3])
        : "r"(a[0]), "r"(a[1]), "r"(a[2]), "r"(a[3]), "r"(b0), "r"(b1));
}

// ---------------- small kernels ----------------
__global__ void zero_cnt() {
    if (threadIdx.x < 27) g_cnt[threadIdx.x] = 0;
}

__global__ void pack_inputs(const float* __restrict__ h, const float* __restrict__ x, int N) {
    size_t idx = (size_t)blockIdx.x * blockDim.x + threadIdx.x;
    size_t total = (size_t)N * CINL;
    if (idx >= total) return;
    int c = (int)(idx % CINL);
    size_t n = idx / CINL;
    float v = (c < HID) ? h[n * HID + c] : x[n * INP + (c - HID)];
    __half hv = __float2half_rn(v);
    g_HX[idx] = hv;
    if (c >= HID) g_RX[idx] = hv;
}

__global__ void pack_wzr(const float* __restrict__ Wz, const float* __restrict__ Wz_pt,
                         const float* __restrict__ Wr, const float* __restrict__ Wr_pt) {
    size_t idx = (size_t)blockIdx.x * blockDim.x + threadIdx.x;
    size_t total = (size_t)256 * KTOT;
    if (idx >= total) return;
    int rem = (int)(idx % KTOT);
    int n = (int)(idx / KTOT);
    int k = rem / CINL;
    int c = rem % CINL;
    float v;
    if (n < HID) v = (k < 27) ? Wz[((size_t)k * CINL + c) * HID + n] : Wz_pt[(size_t)c * HID + n];
    else {
        int m = n - HID;
        v = (k < 27) ? Wr[((size_t)k * CINL + c) * HID + m] : Wr_pt[(size_t)c * HID + m];
    }
    g_Wzr[idx] = __float2half_rn(v);
}

__global__ void pack_wq(const float* __restrict__ Wq, const float* __restrict__ Wq_pt) {
    size_t idx = (size_t)blockIdx.x * blockDim.x + threadIdx.x;
    size_t total = (size_t)128 * KTOT;
    if (idx >= total) return;
    int rem = (int)(idx % KTOT);
    int n = (int)(idx / KTOT);
    int k = rem / CINL;
    int c = rem % CINL;
    float v = (k < 27) ? Wq[((size_t)k * CINL + c) * HID + n] : Wq_pt[(size_t)c * HID + n];
    g_Wq[idx] = __float2half_rn(v);
}

// build per-k lists of rows j that are read as k-neighbors:
// G[k][j] is needed  <=>  nbr[j][26-k] >= 0   (mirror symmetry)
__global__ void build_lists(const int* __restrict__ nbr, int N) {
    const int j = blockIdx.x * blockDim.x + threadIdx.x;
    const int lane = threadIdx.x & 31;
    const bool inb = (j < N);
#pragma unroll 1
    for (int k = 0; k < 27; ++k) {
        bool v = inb && (nbr[(size_t)j * 27 + (26 - k)] >= 0);
        unsigned m = __ballot_sync(0xffffffffu, v);
        int base = 0;
        if (lane == 0 && m) base = atomicAdd(&g_cnt[k], __popc(m));
        base = __shfl_sync(0xffffffffu, base, 0);
        if (v) g_list[(size_t)k * NPT + base + __popc(m & ((1u << lane) - 1u))] = j;
    }
}

// ---------------- G GEMM kernel ----------------
// For each k (0..26: compacted valid rows; 27: identity/pt slot):
//   PASS 1: G[k][j][0:256] = HX[j] @ Wzr[k]   (raw, no bias/activation)
//   PASS 2: G[k][j][0:128] = RX[j] @ Wq[k]
// 16 warps, warp tile 64x32. PASS1: BM=128 (WM=2) x BN=256 (WN=8).
// PASS2: BM=256 (WM=4) x BN=128 (WN=4). 7 chunks of K=64, 4 stages.
template <int PASS, int WM, int WN>
__global__ void __launch_bounds__(512, 1)
gemm_G(int N) {
    constexpr int BM = WM * 64;
    constexpr int BN = WN * 32;
    constexpr int A_BY = BM * 128;
    constexpr int B_BY = BN * 128;
    constexpr int STG = A_BY + B_BY;          // 49152 both
    constexpr int NTILE = (NPT + BM - 1) / BM;
    constexpr int GCOLS = (PASS == 1) ? 256 : 128;

    const int kk = blockIdx.x / NTILE;        // 0..27
    const int t  = blockIdx.x % NTILE;
    const int row0 = t * BM;

    const int cnt = (kk < 27) ? g_cnt[kk] : N;
    if (row0 >= cnt) return;

    extern __shared__ __align__(128) char dynsmem[];

    const int tid  = threadIdx.x;
    const int wid  = tid >> 5;
    const int lane = tid & 31;
    const int wm   = wid / WN;
    const int wn   = wid % WN;
    const int grp  = lane >> 2;
    const int tg   = lane & 3;

    const __half* __restrict__ Asrc = (PASS == 1) ? g_HX : g_RX;
    const __half* __restrict__ WB   = (PASS == 1) ? g_Wzr : g_Wq;
    const int* __restrict__ lst = g_list + (size_t)(kk < 27 ? kk : 0) * NPT;

    const uint32_t dsm_raw = smem_u32(dynsmem);
    const uint32_t dsm = (dsm_raw + 127u) & ~127u;

    // ---- prefetch constants ----
    constexpr int TPR_A = 512 / BM;           // threads per A row
    constexpr int APT   = 8 / TPR_A;          // cp16 per thread (A)
    constexpr int TPR_B = 512 / BN;
    constexpr int BPT   = 8 / TPR_B;
    const int  arow  = tid / TPR_A;
    const int  aseg0 = (tid % TPR_A) * APT;
    const uint32_t axm = (uint32_t)((arow & 7) << 4);
    const int  brow  = tid / TPR_B;
    const int  bseg0 = (tid % TPR_B) * BPT;
    const uint32_t bxm = (uint32_t)((brow & 7) << 4);

    // resolve this CTA's A row id once (k fixed per CTA)
    int id = -1;
    {
        const int gr = row0 + arow;
        if (gr < cnt) id = (kk < 27) ? lst[gr] : gr;
    }
    const int    asz  = (id >= 0) ? 16 : 0;
    const size_t aoff = (size_t)((id >= 0) ? id : 0) * CINL;
    const __half* pbrow = WB + (size_t)brow * KTOT + kk * CINL;

    // ---- ldmatrix lane constants ----
    const int sel = lane >> 3;
    const uint32_t lxm = (uint32_t)((lane & 7) << 4);
    const uint32_t a_row_off =
        (uint32_t)(wm * 64 + (sel & 1) * 8 + (lane & 7)) * 128;
    const uint32_t a_cs16 = (uint32_t)((sel >> 1) * 16);
    const uint32_t b_row_off =
        (uint32_t)(wn * 32 + (sel >> 1) * 8 + (lane & 7)) * 128;
    const uint32_t b_cs16 = (uint32_t)((sel & 1) * 16);

    float acc[4][4][4];
#pragma unroll
    for (int a = 0; a < 4; ++a)
#pragma unroll
        for (int b = 0; b < 4; ++b)
#pragma unroll
            for (int c = 0; c < 4; ++c) acc[a][b][c] = 0.f;

    auto do_prefetch = [&](int c) {
        const int cc = c * 64;
        const uint32_t sb = dsm + (c & 3) * STG;
        const __half* pa = Asrc + aoff + cc + aseg0 * 8;
        const uint32_t da = sb + (uint32_t)arow * 128;
#pragma unroll
        for (int u = 0; u < APT; ++u) {
            const uint32_t so = (uint32_t)((aseg0 + u) * 16) ^ axm;
            cp16(da + so, pa + u * 8, asz);
        }
        const __half* pb = pbrow + cc + bseg0 * 8;
        const uint32_t db = sb + A_BY + (uint32_t)brow * 128;
#pragma unroll
        for (int u = 0; u < BPT; ++u) {
            const uint32_t so = (uint32_t)((bseg0 + u) * 16) ^ bxm;
            cp16(db + so, pb + u * 8, 16);
        }
    };

    do_prefetch(0); CP_COMMIT();
    do_prefetch(1); CP_COMMIT();
    do_prefetch(2); CP_COMMIT();

#pragma unroll 1
    for (int i = 0; i < 7; ++i) {
        CP_WAIT2();
        __syncthreads();
        if (i + 3 < 7) do_prefetch(i + 3);
        CP_COMMIT();

        const uint32_t sb = dsm + (i & 3) * STG;
        const uint32_t aB = sb + a_row_off;
        const uint32_t bB = sb + A_BY + b_row_off;

#pragma unroll
        for (int ks = 0; ks < 4; ++ks) {
            const uint32_t acol = (uint32_t)(ks * 32 + a_cs16) ^ lxm;
            const uint32_t bcol = (uint32_t)(ks * 32 + b_cs16) ^ lxm;
            uint32_t bfr[2][4];
            LDSM_X4(bfr[0][0], bfr[0][1], bfr[0][2], bfr[0][3], bB + bcol);
            LDSM_X4(bfr[1][0], bfr[1][1], bfr[1][2], bfr[1][3], bB + 2048 + bcol);
#pragma unroll
            for (int mt = 0; mt < 4; ++mt) {
                uint32_t afr[4];
                LDSM_X4(afr[0], afr[1], afr[2], afr[3], aB + mt * 2048 + acol);
#pragma unroll
                for (int p = 0; p < 2; ++p) {
                    mma16816(acc[mt][2 * p],     afr, bfr[p][0], bfr[p][1]);
                    mma16816(acc[mt][2 * p + 1], afr, bfr[p][2], bfr[p][3]);
                }
            }
        }
    }

    // ---- epilogue: store raw fp16 rows to G ----
#pragma unroll
    for (int mt = 0; mt < 4; ++mt) {
#pragma unroll
        for (int half = 0; half < 2; ++half) {
            const int rl = wm * 64 + mt * 16 + grp + half * 8;
            const int gr = row0 + rl;
            if (gr >= cnt) continue;
            const int j = (kk < 27) ? lst[gr] : gr;
            __half* gbase = g_G + ((size_t)kk * NPT + j) * GCOLS;
#pragma unroll
            for (int nt = 0; nt < 4; ++nt) {
                const int lc = wn * 32 + nt * 8 + tg * 2;
                const __half2 hv = __floats2half2_rn(acc[mt][nt][half * 2],
                                                     acc[mt][nt][half * 2 + 1]);
                *reinterpret_cast<__half2*>(gbase + lc) = hv;
            }
        }
    }
}

// ---------------- reduce kernels ----------------
__device__ __forceinline__ void acc_u4(float* acc, uint4 v) {
    const __half2* p = reinterpret_cast<const __half2*>(&v);
#pragma unroll
    for (int q = 0; q < 4; ++q) {
        float2 f = __half22float2(p[q]);
        acc[2 * q]     += f.x;
        acc[2 * q + 1] += f.y;
    }
}

// one warp per point: z|r pre-activations -> g_Z, g_RX
__global__ void __launch_bounds__(256, 8)
reduce_zr(const int* __restrict__ nbr, const float* __restrict__ h,
          const float* __restrict__ bz, const float* __restrict__ br, int N) {
    const int i = blockIdx.x * 8 + (threadIdx.x >> 5);
    if (i >= N) return;
    const int lane = threadIdx.x & 31;

    float acc[8];
#pragma unroll
    for (int e = 0; e < 8; ++e) acc[e] = 0.f;

    const int* nb = nbr + (size_t)i * 27;
#pragma unroll 1
    for (int k = 0; k < 27; ++k) {
        const int j = nb[k];
        if (j >= 0) {
            uint4 v = __ldg(reinterpret_cast<const uint4*>(
                          g_G + ((size_t)k * NPT + j) * 256) + lane);
            acc_u4(acc, v);
        }
    }
    {
        uint4 v = __ldg(reinterpret_cast<const uint4*>(
                      g_G + ((size_t)27 * NPT + i) * 256) + lane);
        acc_u4(acc, v);
    }

    const int c0 = lane * 8;
    if (lane < 16) {
#pragma unroll
        for (int e = 0; e < 8; ++e) {
            const int c = c0 + e;
            g_Z[(size_t)i * HID + c] = 1.f / (1.f + __expf(-(acc[e] + __ldg(&bz[c]))));
        }
    } else {
        const int cr0 = c0 - 128;
#pragma unroll
        for (int e = 0; e < 8; ++e) {
            const int c = cr0 + e;
            const float r = 1.f / (1.f + __expf(-(acc[e] + __ldg(&br[c]))));
            g_RX[(size_t)i * CINL + c] = __float2half_rn(r * h[(size_t)i * HID + c]);
        }
    }
}

// one warp per point: q -> GRU blend -> out
__global__ void __launch_bounds__(256, 8)
reduce_q(const int* __restrict__ nbr, const float* __restrict__ h,
         const float* __restrict__ bq, float* __restrict__ out, int N) {
    const int i = blockIdx.x * 8 + (threadIdx.x >> 5);
    if (i >= N) return;
    const int lane = threadIdx.x & 31;

    float acc[4];
#pragma unroll
    for (int e = 0; e < 4; ++e) acc[e] = 0.f;

    const int* nb = nbr + (size_t)i * 27;
#pragma unroll 1
    for (int k = 0; k < 27; ++k) {
        const int j = nb[k];
        if (j >= 0) {
            uint2 v = __ldg(reinterpret_cast<const uint2*>(
                          g_G + ((size_t)k * NPT + j) * 128) + lane);
            const __half2* p = reinterpret_cast<const __half2*>(&v);
            float2 f0 = __half22float2(p[0]);
            float2 f1 = __half22float2(p[1]);
            acc[0] += f0.x; acc[1] += f0.y; acc[2] += f1.x; acc[3] += f1.y;
        }
    }
    {
        uint2 v = __ldg(reinterpret_cast<const uint2*>(
                      g_G + ((size_t)27 * NPT + i) * 128) + lane);
        const __half2* p = reinterpret_cast<const __half2*>(&v);
        float2 f0 = __half22float2(p[0]);
        float2 f1 = __half22float2(p[1]);
        acc[0] += f0.x; acc[1] += f0.y; acc[2] += f1.x; acc[3] += f1.y;
    }

#pragma unroll
    for (int e = 0; e < 4; ++e) {
        const int c = lane * 4 + e;
        const float q  = tanhf(acc[e] + __ldg(&bq[c]));
        const float z  = g_Z[(size_t)i * HID + c];
        const float hv = h[(size_t)i * HID + c];
        out[(size_t)i * HID + c] = fmaf(z, q - hv, hv);
    }
}

// ---------------- launch ----------------
extern "C" void kernel_launch(void* const* d_in, const int* in_sizes, int n_in,
                              void* d_out, int out_size) {
    const float* h     = (const float*)d_in[0];
    const float* x     = (const float*)d_in[1];
    const int*   nbr   = (const int*)  d_in[2];
    const float* Wz    = (const float*)d_in[3];
    const float* Wz_pt = (const float*)d_in[4];
    const float* bz    = (const float*)d_in[5];
    const float* Wr    = (const float*)d_in[6];
    const float* Wr_pt = (const float*)d_in[7];
    const float* br    = (const float*)d_in[8];
    const float* Wq    = (const float*)d_in[9];
    const float* Wq_pt = (const float*)d_in[10];
    const float* bq    = (const float*)d_in[11];

    const int N = in_sizes[0] / HID;
    const int SMEM = 4 * 49152 + 128;   // 196736

    cudaFuncSetAttribute(gemm_G<1, 2, 8>, cudaFuncAttributeMaxDynamicSharedMemorySize, SMEM);
    cudaFuncSetAttribute(gemm_G<2, 4, 4>, cudaFuncAttributeMaxDynamicSharedMemorySize, SMEM);

    zero_cnt<<<1, 32>>>();
    {
        size_t total = (size_t)N * CINL;
        pack_inputs<<<(unsigned)((total + 255) / 256), 256>>>(h, x, N);
    }
    {
        size_t total = (size_t)256 * KTOT;
        pack_wzr<<<(unsigned)((total + 255) / 256), 256>>>(Wz, Wz_pt, Wr, Wr_pt);
    }
    {
        size_t total = (size_t)128 * KTOT;
        pack_wq<<<(unsigned)((total + 255) / 256), 256>>>(Wq, Wq_pt);
    }
    build_lists<<<(N + 255) / 256, 256>>>(nbr, N);

    constexpr int NTILE1 = (NPT + 127) / 128;   // 938
    constexpr int NTILE2 = (NPT + 255) / 256;   // 469

    gemm_G<1, 2, 8><<<28 * NTILE1, 512, SMEM>>>(N);
    reduce_zr<<<(N + 7) / 8, 256>>>(nbr, h, bz, br, N);
    gemm_G<2, 4, 4><<<28 * NTILE2, 512, SMEM>>>(N);
    reduce_q<<<(N + 7) / 8, 256>>>(nbr, h, bq, (float*)d_out, N);
}

// round 10
// speedup vs baseline: 1.8469x; 1.0020x over previous
#include <cuda_runtime.h>
#include <cuda_fp16.h>
#include <cstdint>

#define NPT   120000
#define HID   128
#define INP   320
#define CINL  448
#define KOFF  28
#define KTOT  (KOFF * CINL)     // 12544

// ---------------- device scratch ----------------
__device__ __half g_HX [(size_t)NPT * CINL];
__device__ __half g_RX [(size_t)NPT * CINL];
__device__ float  g_Z  [(size_t)NPT * HID];
__device__ __half g_Wzr[(size_t)256 * KTOT];   // [n][k*448+c]  n<128: z, n>=128: r
__device__ __half g_Wq [(size_t)128 * KTOT];   // [n][k*448+c]
// G buffer: pass1 uses [28][NPT][256] halves; pass2 reuses as [28][NPT][128]
__device__ __half g_G  [(size_t)KOFF * NPT * 256];
__device__ int    g_list[(size_t)27 * NPT];
__device__ int    g_cnt[27];

// ---------------- asm helpers ----------------
__device__ __forceinline__ uint32_t smem_u32(const void* p) {
    uint32_t a;
    asm("{ .reg .u64 t; cvta.to.shared.u64 t, %1; cvt.u32.u64 %0, t; }" : "=r"(a) : "l"(p));
    return a;
}
__device__ __forceinline__ void cp16(uint32_t dst, const void* src, int sz) {
    asm volatile("cp.async.cg.shared.global [%0], [%1], 16, %2;"
                 :: "r"(dst), "l"(src), "r"(sz) : "memory");
}
#define CP_COMMIT() asm volatile("cp.async.commit_group;" ::: "memory")
#define CP_WAIT2()  asm volatile("cp.async.wait_group 2;" ::: "memory")

#define LDSM_X4(r0, r1, r2, r3, addr) \
    asm volatile("ldmatrix.sync.aligned.m8n8.x4.shared.b16 {%0,%1,%2,%3}, [%4];" \
        : "=r"(r0), "=r"(r1), "=r"(r2), "=r"(r3) : "r"(addr))

__device__ __forceinline__ void mma16816(float* d, const uint32_t* a, uint32_t b0, uint32_t b1) {
    asm volatile(
        "mma.sync.aligned.m16n8k16.row.col.f32.f16.f16.f32 "
        "{%0,%1,%2,%3}, {%4,%5,%6,%7}, {%8,%9}, {%0,%1,%2,%3};"
        : "+f"(d[0]), "+f"(d[1]), "+f"(d[2]), "+f"(d[3])
        : "r"(a[0]), "r"(a[1]), "r"(a[2]), "r"(a[3]), "r"(b0), "r"(b1));
}

// ---------------- small kernels ----------------
__global__ void zero_cnt() {
    if (threadIdx.x < 27) g_cnt[threadIdx.x] = 0;
}

__global__ void pack_inputs(const float* __restrict__ h, const float* __restrict__ x, int N) {
    size_t idx = (size_t)blockIdx.x * blockDim.x + threadIdx.x;
    size_t total = (size_t)N * CINL;
    if (idx >= total) return;
    int c = (int)(idx % CINL);
    size_t n = idx / CINL;
    float v = (c < HID) ? h[n * HID + c] : x[n * INP + (c - HID)];
    __half hv = __float2half_rn(v);
    g_HX[idx] = hv;
    if (c >= HID) g_RX[idx] = hv;
}

__global__ void pack_wzr(const float* __restrict__ Wz, const float* __restrict__ Wz_pt,
                         const float* __restrict__ Wr, const float* __restrict__ Wr_pt) {
    size_t idx = (size_t)blockIdx.x * blockDim.x + threadIdx.x;
    size_t total = (size_t)256 * KTOT;
    if (idx >= total) return;
    int rem = (int)(idx % KTOT);
    int n = (int)(idx / KTOT);
    int k = rem / CINL;
    int c = rem % CINL;
    float v;
    if (n < HID) v = (k < 27) ? Wz[((size_t)k * CINL + c) * HID + n] : Wz_pt[(size_t)c * HID + n];
    else {
        int m = n - HID;
        v = (k < 27) ? Wr[((size_t)k * CINL + c) * HID + m] : Wr_pt[(size_t)c * HID + m];
    }
    g_Wzr[idx] = __float2half_rn(v);
}

__global__ void pack_wq(const float* __restrict__ Wq, const float* __restrict__ Wq_pt) {
    size_t idx = (size_t)blockIdx.x * blockDim.x + threadIdx.x;
    size_t total = (size_t)128 * KTOT;
    if (idx >= total) return;
    int rem = (int)(idx % KTOT);
    int n = (int)(idx / KTOT);
    int k = rem / CINL;
    int c = rem % CINL;
    float v = (k < 27) ? Wq[((size_t)k * CINL + c) * HID + n] : Wq_pt[(size_t)c * HID + n];
    g_Wq[idx] = __float2half_rn(v);
}

// build per-k lists of rows j that are read as k-neighbors:
// G[k][j] is needed  <=>  nbr[j][26-k] >= 0   (mirror symmetry)
__global__ void build_lists(const int* __restrict__ nbr, int N) {
    const int j = blockIdx.x * blockDim.x + threadIdx.x;
    const int lane = threadIdx.x & 31;
    const bool inb = (j < N);
#pragma unroll 1
    for (int k = 0; k < 27; ++k) {
        bool v = inb && (nbr[(size_t)j * 27 + (26 - k)] >= 0);
        unsigned m = __ballot_sync(0xffffffffu, v);
        int base = 0;
        if (lane == 0 && m) base = atomicAdd(&g_cnt[k], __popc(m));
        base = __shfl_sync(0xffffffffu, base, 0);
        if (v) g_list[(size_t)k * NPT + base + __popc(m & ((1u << lane) - 1u))] = j;
    }
}

// ---------------- G GEMM kernel ----------------
// For each k (0..26: compacted valid rows; 27: identity/pt slot):
//   PASS 1: G[k][j][0:256] = HX[j] @ Wzr[k]   (raw, no bias/activation)
//   PASS 2: G[k][j][0:128] = RX[j] @ Wq[k]
// 16 warps, warp tile 64x32. PASS1: BM=128 (WM=2) x BN=256 (WN=8).
// PASS2: BM=256 (WM=4) x BN=128 (WN=4). 7 chunks of K=64, 4 stages.
template <int PASS, int WM, int WN>
__global__ void __launch_bounds__(512, 1)
gemm_G(int N) {
    constexpr int BM = WM * 64;
    constexpr int BN = WN * 32;
    constexpr int A_BY = BM * 128;
    constexpr int B_BY = BN * 128;
    constexpr int STG = A_BY + B_BY;          // 49152 both
    constexpr int NTILE = (NPT + BM - 1) / BM;
    constexpr int GCOLS = (PASS == 1) ? 256 : 128;

    const int kk = blockIdx.x / NTILE;        // 0..27
    const int t  = blockIdx.x % NTILE;
    const int row0 = t * BM;

    const int cnt = (kk < 27) ? g_cnt[kk] : N;
    if (row0 >= cnt) return;

    extern __shared__ __align__(128) char dynsmem[];

    const int tid  = threadIdx.x;
    const int wid  = tid >> 5;
    const int lane = tid & 31;
    const int wm   = wid / WN;
    const int wn   = wid % WN;
    const int grp  = lane >> 2;
    const int tg   = lane & 3;

    const __half* __restrict__ Asrc = (PASS == 1) ? g_HX : g_RX;
    const __half* __restrict__ WB   = (PASS == 1) ? g_Wzr : g_Wq;
    const int* __restrict__ lst = g_list + (size_t)(kk < 27 ? kk : 0) * NPT;

    const uint32_t dsm_raw = smem_u32(dynsmem);
    const uint32_t dsm = (dsm_raw + 127u) & ~127u;

    // ---- prefetch constants ----
    constexpr int TPR_A = 512 / BM;           // threads per A row
    constexpr int APT   = 8 / TPR_A;          // cp16 per thread (A)
    constexpr int TPR_B = 512 / BN;
    constexpr int BPT   = 8 / TPR_B;
    const int  arow  = tid / TPR_A;
    const int  aseg0 = (tid % TPR_A) * APT;
    const uint32_t axm = (uint32_t)((arow & 7) << 4);
    const int  brow  = tid / TPR_B;
    const int  bseg0 = (tid % TPR_B) * BPT;
    const uint32_t bxm = (uint32_t)((brow & 7) << 4);

    // resolve this CTA's A row id once (k fixed per CTA)
    int id = -1;
    {
        const int gr = row0 + arow;
        if (gr < cnt) id = (kk < 27) ? lst[gr] : gr;
    }
    const int    asz  = (id >= 0) ? 16 : 0;
    const size_t aoff = (size_t)((id >= 0) ? id : 0) * CINL;
    const __half* pbrow = WB + (size_t)brow * KTOT + kk * CINL;

    // ---- ldmatrix lane constants ----
    const int sel = lane >> 3;
    const uint32_t lxm = (uint32_t)((lane & 7) << 4);
    const uint32_t a_row_off =
        (uint32_t)(wm * 64 + (sel & 1) * 8 + (lane & 7)) * 128;
    const uint32_t a_cs16 = (uint32_t)((sel >> 1) * 16);
    const uint32_t b_row_off =
        (uint32_t)(wn * 32 + (sel >> 1) * 8 + (lane & 7)) * 128;
    const uint32_t b_cs16 = (uint32_t)((sel & 1) * 16);

    float acc[4][4][4];
#pragma unroll
    for (int a = 0; a < 4; ++a)
#pragma unroll
        for (int b = 0; b < 4; ++b)
#pragma unroll
            for (int c = 0; c < 4; ++c) acc[a][b][c] = 0.f;

    auto do_prefetch = [&](int c) {
        const int cc = c * 64;
        const uint32_t sb = dsm + (c & 3) * STG;
        const __half* pa = Asrc + aoff + cc + aseg0 * 8;
        const uint32_t da = sb + (uint32_t)arow * 128;
#pragma unroll
        for (int u = 0; u < APT; ++u) {
            const uint32_t so = (uint32_t)((aseg0 + u) * 16) ^ axm;
            cp16(da + so, pa + u * 8, asz);
        }
        const __half* pb = pbrow + cc + bseg0 * 8;
        const uint32_t db = sb + A_BY + (uint32_t)brow * 128;
#pragma unroll
        for (int u = 0; u < BPT; ++u) {
            const uint32_t so = (uint32_t)((bseg0 + u) * 16) ^ bxm;
            cp16(db + so, pb + u * 8, 16);
        }
    };

    do_prefetch(0); CP_COMMIT();
    do_prefetch(1); CP_COMMIT();
    do_prefetch(2); CP_COMMIT();

#pragma unroll 1
    for (int i = 0; i < 7; ++i) {
        CP_WAIT2();
        __syncthreads();
        if (i + 3 < 7) do_prefetch(i + 3);
        CP_COMMIT();

        const uint32_t sb = dsm + (i & 3) * STG;
        const uint32_t aB = sb + a_row_off;
        const uint32_t bB = sb + A_BY + b_row_off;

#pragma unroll
        for (int ks = 0; ks < 4; ++ks) {
            const uint32_t acol = (uint32_t)(ks * 32 + a_cs16) ^ lxm;
            const uint32_t bcol = (uint32_t)(ks * 32 + b_cs16) ^ lxm;
            uint32_t bfr[2][4];
            LDSM_X4(bfr[0][0], bfr[0][1], bfr[0][2], bfr[0][3], bB + bcol);
            LDSM_X4(bfr[1][0], bfr[1][1], bfr[1][2], bfr[1][3], bB + 2048 + bcol);
#pragma unroll
            for (int mt = 0; mt < 4; ++mt) {
                uint32_t afr[4];
                LDSM_X4(afr[0], afr[1], afr[2], afr[3], aB + mt * 2048 + acol);
#pragma unroll
                for (int p = 0; p < 2; ++p) {
                    mma16816(acc[mt][2 * p],     afr, bfr[p][0], bfr[p][1]);
                    mma16816(acc[mt][2 * p + 1], afr, bfr[p][2], bfr[p][3]);
                }
            }
        }
    }

    // ---- epilogue: store raw fp16 rows to G ----
#pragma unroll
    for (int mt = 0; mt < 4; ++mt) {
#pragma unroll
        for (int half = 0; half < 2; ++half) {
            const int rl = wm * 64 + mt * 16 + grp + half * 8;
            const int gr = row0 + rl;
            if (gr >= cnt) continue;
            const int j = (kk < 27) ? lst[gr] : gr;
            __half* gbase = g_G + ((size_t)kk * NPT + j) * GCOLS;
#pragma unroll
            for (int nt = 0; nt < 4; ++nt) {
                const int lc = wn * 32 + nt * 8 + tg * 2;
                const __half2 hv = __floats2half2_rn(acc[mt][nt][half * 2],
                                                     acc[mt][nt][half * 2 + 1]);
                *reinterpret_cast<__half2*>(gbase + lc) = hv;
            }
        }
    }
}

// ---------------- reduce kernels ----------------
__device__ __forceinline__ void acc_u4(float* acc, uint4 v) {
    const __half2* p = reinterpret_cast<const __half2*>(&v);
#pragma unroll
    for (int q = 0; q < 4; ++q) {
        float2 f = __half22float2(p[q]);
        acc[2 * q]     += f.x;
        acc[2 * q + 1] += f.y;
    }
}

// one warp per point: z|r pre-activations -> g_Z, g_RX
// grouped-unrolled gather (9 predicated loads in flight) for MLP
__global__ void __launch_bounds__(256)
reduce_zr(const int* __restrict__ nbr, const float* __restrict__ h,
          const float* __restrict__ bz, const float* __restrict__ br, int N) {
    const int i = blockIdx.x * 8 + (threadIdx.x >> 5);
    if (i >= N) return;
    const int lane = threadIdx.x & 31;

    float acc[8];
#pragma unroll
    for (int e = 0; e < 8; ++e) acc[e] = 0.f;

    int idx[27];
    const int* nb = nbr + (size_t)i * 27;
#pragma unroll
    for (int k = 0; k < 27; ++k) idx[k] = nb[k];

    const uint4 z4 = make_uint4(0u, 0u, 0u, 0u);
#pragma unroll 1
    for (int kg = 0; kg < 27; kg += 9) {
        uint4 v[9];
#pragma unroll
        for (int u = 0; u < 9; ++u) {
            const int j = idx[kg + u];
            v[u] = z4;
            if (j >= 0)
                v[u] = __ldg(reinterpret_cast<const uint4*>(
                           g_G + ((size_t)(kg + u) * NPT + j) * 256) + lane);
        }
#pragma unroll
        for (int u = 0; u < 9; ++u) acc_u4(acc, v[u]);
    }
    {
        uint4 v = __ldg(reinterpret_cast<const uint4*>(
                      g_G + ((size_t)27 * NPT + i) * 256) + lane);
        acc_u4(acc, v);
    }

    const int c0 = lane * 8;
    if (lane < 16) {
#pragma unroll
        for (int e = 0; e < 8; ++e) {
            const int c = c0 + e;
            g_Z[(size_t)i * HID + c] = 1.f / (1.f + __expf(-(acc[e] + __ldg(&bz[c]))));
        }
    } else {
        const int cr0 = c0 - 128;
#pragma unroll
        for (int e = 0; e < 8; ++e) {
            const int c = cr0 + e;
            const float r = 1.f / (1.f + __expf(-(acc[e] + __ldg(&br[c]))));
            g_RX[(size_t)i * CINL + c] = __float2half_rn(r * h[(size_t)i * HID + c]);
        }
    }
}

// one warp per point: q -> GRU blend -> out
__global__ void __launch_bounds__(256)
reduce_q(const int* __restrict__ nbr, const float* __restrict__ h,
         const float* __restrict__ bq, float* __restrict__ out, int N) {
    const int i = blockIdx.x * 8 + (threadIdx.x >> 5);
    if (i >= N) return;
    const int lane = threadIdx.x & 31;

    float acc[4];
#pragma unroll
    for (int e = 0; e < 4; ++e) acc[e] = 0.f;

    int idx[27];
    const int* nb = nbr + (size_t)i * 27;
#pragma unroll
    for (int k = 0; k < 27; ++k) idx[k] = nb[k];

    const uint2 z2 = make_uint2(0u, 0u);
#pragma unroll 1
    for (int kg = 0; kg < 27; kg += 9) {
        uint2 v[9];
#pragma unroll
        for (int u = 0; u < 9; ++u) {
            const int j = idx[kg + u];
            v[u] = z2;
            if (j >= 0)
                v[u] = __ldg(reinterpret_cast<const uint2*>(
                           g_G + ((size_t)(kg + u) * NPT + j) * 128) + lane);
        }
#pragma unroll
        for (int u = 0; u < 9; ++u) {
            const __half2* p = reinterpret_cast<const __half2*>(&v[u]);
            float2 f0 = __half22float2(p[0]);
            float2 f1 = __half22float2(p[1]);
            acc[0] += f0.x; acc[1] += f0.y; acc[2] += f1.x; acc[3] += f1.y;
        }
    }
    {
        uint2 v = __ldg(reinterpret_cast<const uint2*>(
                      g_G + ((size_t)27 * NPT + i) * 128) + lane);
        const __half2* p = reinterpret_cast<const __half2*>(&v);
        float2 f0 = __half22float2(p[0]);
        float2 f1 = __half22float2(p[1]);
        acc[0] += f0.x; acc[1] += f0.y; acc[2] += f1.x; acc[3] += f1.y;
    }

#pragma unroll
    for (int e = 0; e < 4; ++e) {
        const int c = lane * 4 + e;
        const float q  = tanhf(acc[e] + __ldg(&bq[c]));
        const float z  = g_Z[(size_t)i * HID + c];
        const float hv = h[(size_t)i * HID + c];
        out[(size_t)i * HID + c] = fmaf(z, q - hv, hv);
    }
}

// ---------------- launch ----------------
extern "C" void kernel_launch(void* const* d_in, const int* in_sizes, int n_in,
                              void* d_out, int out_size) {
    const float* h     = (const float*)d_in[0];
    const float* x     = (const float*)d_in[1];
    const int*   nbr   = (const int*)  d_in[2];
    const float* Wz    = (const float*)d_in[3];
    const float* Wz_pt = (const float*)d_in[4];
    const float* bz    = (const float*)d_in[5];
    const float* Wr    = (const float*)d_in[6];
    const float* Wr_pt = (const float*)d_in[7];
    const float* br    = (const float*)d_in[8];
    const float* Wq    = (const float*)d_in[9];
    const float* Wq_pt = (const float*)d_in[10];
    const float* bq    = (const float*)d_in[11];

    const int N = in_sizes[0] / HID;
    const int SMEM = 4 * 49152 + 128;   // 196736

    cudaFuncSetAttribute(gemm_G<1, 2, 8>, cudaFuncAttributeMaxDynamicSharedMemorySize, SMEM);
    cudaFuncSetAttribute(gemm_G<2, 4, 4>, cudaFuncAttributeMaxDynamicSharedMemorySize, SMEM);

    zero_cnt<<<1, 32>>>();
    {
        size_t total = (size_t)N * CINL;
        pack_inputs<<<(unsigned)((total + 255) / 256), 256>>>(h, x, N);
    }
    {
        size_t total = (size_t)256 * KTOT;
        pack_wzr<<<(unsigned)((total + 255) / 256), 256>>>(Wz, Wz_pt, Wr, Wr_pt);
    }
    {
        size_t total = (size_t)128 * KTOT;
        pack_wq<<<(unsigned)((total + 255) / 256), 256>>>(Wq, Wq_pt);
    }
    build_lists<<<(N + 255) / 256, 256>>>(nbr, N);

    constexpr int NTILE1 = (NPT + 127) / 128;   // 938
    constexpr int NTILE2 = (NPT + 255) / 256;   // 469

    gemm_G<1, 2, 8><<<28 * NTILE1, 512, SMEM>>>(N);
    reduce_zr<<<(N + 7) / 8, 256>>>(nbr, h, bz, br, N);
    gemm_G<2, 4, 4><<<28 * NTILE2, 512, SMEM>>>(N);
    reduce_q<<<(N + 7) / 8, 256>>>(nbr, h, bq, (float*)d_out, N);
}